// round 17
// baseline (speedup 1.0000x reference)
#include <cuda_runtime.h>
#include <math.h>

#define NB 8
#define NS 512
#define NE 64
#define NH 8
#define NW 8
#define QB  (NB * NH * 2)     // 128 attention blocks (half-head each)
#define TBLOCKS 16            // Wo-transpose rider blocks

// scratch
__device__ float g_ctx[NB * NS * NE];      // attention context [B,S,E]
__device__ float g_WT[NE * NE];            // WT[e*64+o] = Wo[o*64+e]

typedef unsigned long long u64;

__device__ __forceinline__ u64 pk2(float lo, float hi) {
    u64 r; asm("mov.b64 %0,{%1,%2};" : "=l"(r) : "f"(lo), "f"(hi)); return r;
}
__device__ __forceinline__ void unpk2(u64 v, float& lo, float& hi) {
    asm("mov.b64 {%0,%1},%2;" : "=f"(lo), "=f"(hi) : "l"(v));
}
__device__ __forceinline__ void ffma2(u64& d, u64 a, u64 b) {
    asm("fma.rn.f32x2 %0,%1,%2,%0;" : "+l"(d) : "l"(a), "l"(b));
}
__device__ __forceinline__ void fadd2(u64& d, u64 a) {
    asm("add.rn.f32x2 %0,%0,%1;" : "+l"(d) : "l"(a));
}

// ---------------------------------------------------------------------------
// Kernel 1: fused q-build + self-attention.
//   Blocks [0,128): block = (bh, half). Phase A builds the head's full q[512][8]
//   in smem (2 rows/thread, __cosf). Phase B: lane = one query row; the key
//   loop index is warp-UNIFORM, so every key LDS.128 is a broadcast (N=1, no
//   crossbar penalty) serving 32 rows at once -> 32x less smem traffic.
//   No softmax max pass (|score| <= sqrt(8)). Packed f32x2 FMA, no shuffles.
//   Blocks [128,144): rider transpose Wo -> g_WT (hidden under attention).
// ---------------------------------------------------------------------------
__global__ __launch_bounds__(256)
void qattn_kernel(const float* __restrict__ x, const float* __restrict__ theta,
                  const float* __restrict__ Wo)
{
    const int blk = blockIdx.x;
    const int tid = threadIdx.x;

    if (blk >= QB) {
        const int i = (blk - QB) * 256 + tid;
        const int o = i >> 6, e = i & 63;          // read coalesced
        g_WT[e * NE + o] = Wo[i];
        return;
    }

    __shared__ __align__(16) float q[NS][NW];   // 16 KB

    const int half = blk & 1;
    const int bh   = blk >> 1;
    const int b    = bh >> 3, h = bh & 7;

    float th[NW];
#pragma unroll
    for (int k = 0; k < NW; k++) th[k] = __ldg(&theta[k]);

    // ---- Phase A: build q for ALL 512 tokens of this head (2 per thread) ----
    // e[j>=1] = prod_{k<=j} cos(x_k+th_k);  e[0] = prod_{k=1..7} cos(x_k+th_k)
    for (int s = tid; s < NS; s += 256) {
        const float* xp = x + ((b * NS + s) * NE + h * NW);
        const float4 xa = *(const float4*)&xp[0];
        const float4 xb = *(const float4*)&xp[4];
        float c[NW];
        c[0] = __cosf(xa.x + th[0]); c[1] = __cosf(xa.y + th[1]);
        c[2] = __cosf(xa.z + th[2]); c[3] = __cosf(xa.w + th[3]);
        c[4] = __cosf(xb.x + th[4]); c[5] = __cosf(xb.y + th[5]);
        c[6] = __cosf(xb.z + th[6]); c[7] = __cosf(xb.w + th[7]);
        float e[NW];
        float run = c[0];
#pragma unroll
        for (int j = 1; j < NW; j++) { run *= c[j]; e[j] = run; }
        float r = c[NW - 1];
#pragma unroll
        for (int j = NW - 2; j >= 1; j--) r *= c[j];
        e[0] = r;
        *(float4*)&q[s][0] = make_float4(e[0], e[1], e[2], e[3]);
        *(float4*)&q[s][4] = make_float4(e[4], e[5], e[6], e[7]);
    }
    __syncthreads();

    // ---- Phase B: lane = one query row; broadcast key sweep ----
    const int s = half * 256 + tid;               // this lane's query row
    const float scale = 0.35355339059327373f;     // 1/sqrt(8)

    u64 qp[4];
    {
        float4 lo4 = *(const float4*)&q[s][0];
        float4 hi4 = *(const float4*)&q[s][4];
        qp[0] = pk2(lo4.x * scale, lo4.y * scale);
        qp[1] = pk2(lo4.z * scale, lo4.w * scale);
        qp[2] = pk2(hi4.x * scale, hi4.y * scale);
        qp[3] = pk2(hi4.z * scale, hi4.w * scale);
    }

    u64 a2[4] = {0ull, 0ull, 0ull, 0ull};
    float l = 0.f;

#pragma unroll 4
    for (int t = 0; t < NS; t++) {                // t uniform -> broadcast LDS
        ulonglong2 kA = *(const ulonglong2*)&q[t][0];
        ulonglong2 kB = *(const ulonglong2*)&q[t][4];

        u64 d2 = 0ull, d2b = 0ull;
        ffma2(d2,  qp[0], kA.x);
        ffma2(d2b, qp[1], kA.y);
        ffma2(d2,  qp[2], kB.x);
        ffma2(d2b, qp[3], kB.y);
        fadd2(d2, d2b);
        float dl, dh; unpk2(d2, dl, dh);

        const float e = __expf(dl + dh);          // safe: |score| <= 2.83
        l += e;
        const u64 ep = pk2(e, e);
        ffma2(a2[0], ep, kA.x);
        ffma2(a2[1], ep, kA.y);
        ffma2(a2[2], ep, kB.x);
        ffma2(a2[3], ep, kB.y);
    }

    const float inv = 1.f / l;
    float o[NW];
#pragma unroll
    for (int i = 0; i < 4; i++) {
        float lo, hi; unpk2(a2[i], lo, hi);
        o[2 * i] = lo * inv; o[2 * i + 1] = hi * inv;
    }
    float* op = g_ctx + ((b * NS + s) * NE + h * NW);
    *(float4*)&op[0] = make_float4(o[0], o[1], o[2], o[3]);
    *(float4*)&op[4] = make_float4(o[4], o[5], o[6], o[7]);
}

// ---------------------------------------------------------------------------
// Kernel 2: out[r][o] = sum_e ctx[r][e] * WT[e][o] + bo[o]   (4096 x 64 x 64)
// 256 blocks x 16 rows. WT staged in smem once per block. Warp = 2 rows;
// lane owns 2 adjacent outputs per row (LDS.64 conflict-free, R broadcast).
// 16 ffma2 per 4-e iteration -> FMA-bound, not LDS-bound.
// ---------------------------------------------------------------------------
__global__ __launch_bounds__(256)
void proj_kernel(const float* __restrict__ bo, float* __restrict__ out)
{
    __shared__ __align__(16) float WTs[NE * NE];   // 16 KB
    __shared__ __align__(16) float R[16][NE];      // 4 KB

    const int tid = threadIdx.x;
    const int rowbase = blockIdx.x * 16;

    {
        const float4* src = (const float4*)g_WT;
        float4* dst = (float4*)WTs;
#pragma unroll
        for (int i = 0; i < 4; i++)
            dst[tid + 256 * i] = src[tid + 256 * i];
        ((float4*)R)[tid] = ((const float4*)(g_ctx + rowbase * NE))[tid];
    }
    __syncthreads();

    const int warp = tid >> 5, lane = tid & 31;
    const int r0 = warp * 2, r1 = r0 + 1;
    const int o0 = lane * 2;

    const u64 bias = *(const u64*)&bo[o0];
    u64 acc0 = bias, ac20 = 0ull;
    u64 acc1 = bias, ac21 = 0ull;
#pragma unroll
    for (int e = 0; e < NE; e += 4) {
        const float4 c0 = *(const float4*)&R[r0][e];        // broadcast LDS.128
        const float4 c1 = *(const float4*)&R[r1][e];
        const u64 w0 = *(const u64*)&WTs[(e + 0) * NE + o0];
        const u64 w1 = *(const u64*)&WTs[(e + 1) * NE + o0];
        const u64 w2 = *(const u64*)&WTs[(e + 2) * NE + o0];
        const u64 w3 = *(const u64*)&WTs[(e + 3) * NE + o0];
        ffma2(acc0, pk2(c0.x, c0.x), w0);
        ffma2(ac20, pk2(c0.y, c0.y), w1);
        ffma2(acc0, pk2(c0.z, c0.z), w2);
        ffma2(ac20, pk2(c0.w, c0.w), w3);
        ffma2(acc1, pk2(c1.x, c1.x), w0);
        ffma2(ac21, pk2(c1.y, c1.y), w1);
        ffma2(acc1, pk2(c1.z, c1.z), w2);
        ffma2(ac21, pk2(c1.w, c1.w), w3);
    }
    fadd2(acc0, ac20);
    fadd2(acc1, ac21);
    *(u64*)&out[(rowbase + r0) * NE + o0] = acc0;
    *(u64*)&out[(rowbase + r1) * NE + o0] = acc1;
}

extern "C" void kernel_launch(void* const* d_in, const int* in_sizes, int n_in,
                              void* d_out, int out_size)
{
    const float* x     = (const float*)d_in[0];
    const float* theta = (const float*)d_in[1];
    const float* Wo    = (const float*)d_in[2];
    const float* bo    = (const float*)d_in[3];
    float* out = (float*)d_out;

    qattn_kernel<<<QB + TBLOCKS, 256>>>(x, theta, Wo);
    proj_kernel<<<NB * NS / 16, 256>>>(bo, out);
}